// round 4
// baseline (speedup 1.0000x reference)
#include <cuda_runtime.h>
#include <cuda_fp16.h>

#define DT 0.05f
#define N_STEPS 41

typedef unsigned long long u64;

// Global accumulators: [0] = sum(err+eff), [1] = sum(nor). Zero-initialized at
// module load; the LAST block of each launch resets them after reading, so the
// kernel is replay-deterministic under graph capture.
__device__ double g_acc[2] = {0.0, 0.0};
__device__ unsigned int g_count = 0;

// ---- f32x2 packed helpers (SASS FFMA2 — only reachable via PTX) ----
__device__ __forceinline__ u64 pack2(float lo, float hi) {
    u64 r; asm("mov.b64 %0, {%1, %2};" : "=l"(r) : "f"(lo), "f"(hi)); return r;
}
__device__ __forceinline__ void unpack2(u64 v, float& lo, float& hi) {
    asm("mov.b64 {%0, %1}, %2;" : "=f"(lo), "=f"(hi) : "l"(v));
}
__device__ __forceinline__ u64 fma2(u64 a, u64 b, u64 c) {
    u64 d; asm("fma.rn.f32x2 %0, %1, %2, %3;" : "=l"(d) : "l"(a), "l"(b), "l"(c)); return d;
}
__device__ __forceinline__ u64 mul2(u64 a, u64 b) {
    u64 d; asm("mul.rn.f32x2 %0, %1, %2;" : "=l"(d) : "l"(a), "l"(b)); return d;
}

// tanh on a half2 (both lanes), one MUFU op, no conversions.
__device__ __forceinline__ __half2 tanh_h2(__half2 x) {
    unsigned int b = *reinterpret_cast<unsigned int*>(&x);
    asm("tanh.approx.f16x2 %0, %0;" : "+r"(b));
    return *reinterpret_cast<__half2*>(&b);
}

#define NCHAIN 2   // independent SIMD chains per thread (4 tasks/thread)

__global__ void __launch_bounds__(128) sim_kernel(
    const float* __restrict__ omega,
    const float* __restrict__ Wh1, const float* __restrict__ bh1,
    const float* __restrict__ Wh2, const float* __restrict__ bh2,
    const float* __restrict__ Wr1, const float* __restrict__ br1,
    const float* __restrict__ Wr2, const float* __restrict__ br2,
    const float* __restrict__ alpha,
    float* __restrict__ out,
    int n)
{
    const int quarter = n >> 2;        // n divisible by 4 (1048576)
    const int i = blockIdx.x * blockDim.x + threadIdx.x;

    float v1 = 0.0f, v2 = 0.0f;

    if (i < quarter) {
        // ---- shared packed weights (chain-invariant) ----
        float wh1r[16], bh1r[4];
#pragma unroll
        for (int j = 0; j < 16; j++) wh1r[j] = __ldg(Wh1 + j);
#pragma unroll
        for (int j = 0; j < 4; j++)  bh1r[j] = __ldg(bh1 + j);

        __half2 whA[4], whB[4];
#pragma unroll
        for (int j = 0; j < 4; j++) {
            whA[j] = __float2half2_rn(wh1r[4*j + 2]);
            whB[j] = __float2half2_rn(wh1r[4*j + 3]);
        }
        __half2 wh2v[4], bh2v;
#pragma unroll
        for (int j = 0; j < 4; j++) wh2v[j] = __float2half2_rn(__ldg(Wh2 + j));
        bh2v = __float2half2_rn(__ldg(bh2));

        __half2 wrS0[3], wrS1[3], wrZ[3], br1v[3];
#pragma unroll
        for (int j = 0; j < 3; j++) {
            wrS0[j] = __float2half2_rn(__ldg(Wr1 + 3*j + 0));
            wrS1[j] = __float2half2_rn(__ldg(Wr1 + 3*j + 1));
            wrZ[j]  = __float2half2_rn(__ldg(Wr1 + 3*j + 2));
            br1v[j] = __float2half2_rn(__ldg(br1 + j));
        }
        __half2 wr2v[3], br2v;
#pragma unroll
        for (int j = 0; j < 3; j++) wr2v[j] = __float2half2_rn(__ldg(Wr2 + j));
        br2v = __float2half2_rn(__ldg(br2));

        const u64 neg1 = pack2(-1.0f, -1.0f);
        const u64 ten  = pack2(10.0f, 10.0f);
        const u64 c01  = pack2(0.1f, 0.1f);
        const u64 dt2  = pack2(DT, DT);
        const __half2 thr = __float2half2_rn(0.01f);

        // ---- per-chain state ----
        u64 star0[NCHAIN], star1[NCHAIN];
        __half2 c_h[NCHAIN][4];
        u64 s0[NCHAIN], s1[NCHAIN], err[NCHAIN], nor[NCHAIN];
        __half2 eff[NCHAIN];

#pragma unroll
        for (int c = 0; c < NCHAIN; c++) {
            // chain c covers tasks i + (2c)*quarter (lo) and i + (2c+1)*quarter (hi)
            int lo = i + (2*c    ) * quarter;
            int hi = i + (2*c + 1) * quarter;
            float a0 = omega[lo],     b0 = omega[hi];
            float a1 = omega[n + lo], b1 = omega[n + hi];
            star0[c] = pack2(a0, b0);
            star1[c] = pack2(a1, b1);
#pragma unroll
            for (int j = 0; j < 4; j++) {
                float clo = fmaf(wh1r[4*j], a0, fmaf(wh1r[4*j+1], a1, bh1r[j]));
                float chi = fmaf(wh1r[4*j], b0, fmaf(wh1r[4*j+1], b1, bh1r[j]));
                c_h[c][j] = __floats2half2_rn(clo, chi);
            }
            s0[c] = 0ull; s1[c] = 0ull; err[c] = 0ull; nor[c] = 0ull;
            eff[c] = __float2half2_rn(0.0f);
        }

#pragma unroll 1
        for (int t = 0; t < N_STEPS - 1; t++) {
#pragma unroll
            for (int c = 0; c < NCHAIN; c++) {
                // f32x2 outer dynamics
                u64 e0 = fma2(neg1, s0[c], star0[c]);
                u64 e1 = fma2(neg1, s1[c], star1[c]);
                err[c] = fma2(ten, mul2(e0, e0), err[c]);
                err[c] = fma2(e1, e1, err[c]);
                u64 zt = fma2(c01, e1, e0);

                // state -> half2
                float s0lo, s0hi, s1lo, s1hi;
                unpack2(s0[c], s0lo, s0hi);
                unpack2(s1[c], s1lo, s1hi);
                __half2 s0h = __floats2half2_rn(s0lo, s0hi);
                __half2 s1h = __floats2half2_rn(s1lo, s1hi);

                // human MLP (star part folded into c_h)
                __half2 h0 = tanh_h2(__hfma2(whB[0], s1h, __hfma2(whA[0], s0h, c_h[c][0])));
                __half2 h1 = tanh_h2(__hfma2(whB[1], s1h, __hfma2(whA[1], s0h, c_h[c][1])));
                __half2 h2 = tanh_h2(__hfma2(whB[2], s1h, __hfma2(whA[2], s0h, c_h[c][2])));
                __half2 h3 = tanh_h2(__hfma2(whB[3], s1h, __hfma2(whA[3], s0h, c_h[c][3])));
                __half2 z  = tanh_h2(__hfma2(wh2v[3], h3, __hfma2(wh2v[2], h2,
                                     __hfma2(wh2v[1], h1, __hfma2(wh2v[0], h0, bh2v)))));

                // robot MLP
                __half2 r0 = tanh_h2(__hfma2(wrZ[0], z, __hfma2(wrS1[0], s1h, __hfma2(wrS0[0], s0h, br1v[0]))));
                __half2 r1 = tanh_h2(__hfma2(wrZ[1], z, __hfma2(wrS1[1], s1h, __hfma2(wrS0[1], s0h, br1v[1]))));
                __half2 r2 = tanh_h2(__hfma2(wrZ[2], z, __hfma2(wrS1[2], s1h, __hfma2(wrS0[2], s0h, br1v[2]))));
                __half2 ah = __hfma2(wr2v[2], r2, __hfma2(wr2v[1], r1, __hfma2(wr2v[0], r0, br2v)));

                // state update in f32x2
                float2 af = __half22float2(ah);
                s0[c] = fma2(dt2, s1[c], s0[c]);
                s1[c] = fma2(dt2, pack2(af.x, af.y), s1[c]);

                // eff: half2 compare gives 1.0/0.0 per lane
                eff[c] = __hadd2(eff[c], __hgt2(__habs2(z), thr));

                // nor in f32x2
                float2 zf = __half22float2(z);
                u64 d = fma2(neg1, pack2(zf.x, zf.y), zt);
                nor[c] = fma2(d, d, nor[c]);
            }
        }

#pragma unroll
        for (int c = 0; c < NCHAIN; c++) {
            u64 e0 = fma2(neg1, s0[c], star0[c]);
            u64 e1 = fma2(neg1, s1[c], star1[c]);
            err[c] = fma2(ten, mul2(e0, e0), err[c]);
            err[c] = fma2(e1, e1, err[c]);

            float err_lo, err_hi, nor_lo, nor_hi;
            unpack2(err[c], err_lo, err_hi);
            unpack2(nor[c], nor_lo, nor_hi);
            float2 efff = __half22float2(eff[c]);
            v1 += (err_lo + efff.x) + (err_hi + efff.y);
            v2 += nor_lo + nor_hi;
        }
    }

    // warp reduce
#pragma unroll
    for (int off = 16; off > 0; off >>= 1) {
        v1 += __shfl_down_sync(0xFFFFFFFFu, v1, off);
        v2 += __shfl_down_sync(0xFFFFFFFFu, v2, off);
    }

    __shared__ float s1buf[4];
    __shared__ float s2buf[4];
    int lane = threadIdx.x & 31;
    int wid  = threadIdx.x >> 5;
    if (lane == 0) { s1buf[wid] = v1; s2buf[wid] = v2; }
    __syncthreads();

    __shared__ bool is_last;
    if (threadIdx.x == 0) {
        float a1 = s1buf[0] + s1buf[1] + s1buf[2] + s1buf[3];
        float a2 = s2buf[0] + s2buf[1] + s2buf[2] + s2buf[3];
        atomicAdd(&g_acc[0], (double)a1);
        atomicAdd(&g_acc[1], (double)a2);
        __threadfence();
        unsigned int ticket = atomicAdd(&g_count, 1u);
        is_last = (ticket == gridDim.x - 1);
    }
    __syncthreads();

    // Tail block: finalize and reset accumulators for the next graph replay.
    if (is_last && threadIdx.x == 0) {
        double tot = (g_acc[0] + (double)alpha[0] * g_acc[1]) / (double)n;
        out[0] = (float)tot;
        g_acc[0] = 0.0;
        g_acc[1] = 0.0;
        g_count  = 0u;
        __threadfence();
    }
}

extern "C" void kernel_launch(void* const* d_in, const int* in_sizes, int n_in,
                              void* d_out, int out_size) {
    const float* omega = (const float*)d_in[0];
    const float* Wh1   = (const float*)d_in[1];
    const float* bh1   = (const float*)d_in[2];
    const float* Wh2   = (const float*)d_in[3];
    const float* bh2   = (const float*)d_in[4];
    const float* Wr1   = (const float*)d_in[5];
    const float* br1   = (const float*)d_in[6];
    const float* Wr2   = (const float*)d_in[7];
    const float* br2   = (const float*)d_in[8];
    const float* alpha = (const float*)d_in[9];
    float* out = (float*)d_out;

    int n = in_sizes[0] / 2;  // omega is [2, N]
    int quarter = n >> 2;

    int threads = 128;
    int blocks = (quarter + threads - 1) / threads;
    sim_kernel<<<blocks, threads>>>(omega, Wh1, bh1, Wh2, bh2, Wr1, br1, Wr2, br2,
                                    alpha, out, n);
}

// round 5
// speedup vs baseline: 1.0206x; 1.0206x over previous
#include <cuda_runtime.h>
#include <cuda_fp16.h>

#define DT 0.05f
#define N_STEPS 41

typedef unsigned long long u64;

// Global accumulators: [0] = sum(err+eff), [1] = sum(nor). Zero-initialized at
// module load; the LAST block of each launch resets them after reading, so the
// kernel is replay-deterministic under graph capture.
__device__ double g_acc[2] = {0.0, 0.0};
__device__ unsigned int g_count = 0;

// ---- f32x2 packed helpers (SASS FFMA2 — only reachable via PTX) ----
__device__ __forceinline__ u64 pack2(float lo, float hi) {
    u64 r; asm("mov.b64 %0, {%1, %2};" : "=l"(r) : "f"(lo), "f"(hi)); return r;
}
__device__ __forceinline__ void unpack2(u64 v, float& lo, float& hi) {
    asm("mov.b64 {%0, %1}, %2;" : "=f"(lo), "=f"(hi) : "l"(v));
}
__device__ __forceinline__ u64 fma2(u64 a, u64 b, u64 c) {
    u64 d; asm("fma.rn.f32x2 %0, %1, %2, %3;" : "=l"(d) : "l"(a), "l"(b), "l"(c)); return d;
}

// tanh on a half2 (both lanes), one MUFU op, no conversions.
__device__ __forceinline__ __half2 tanh_h2(__half2 x) {
    unsigned int b = *reinterpret_cast<unsigned int*>(&x);
    asm("tanh.approx.f16x2 %0, %0;" : "+r"(b));
    return *reinterpret_cast<__half2*>(&b);
}

// Broadcast one lane of a packed half2 — ptxas folds these into HFMA2
// half-lane-select source modifiers (.H0_H0 / .H1_H1), costing no instruction.
__device__ __forceinline__ __half2 lo2(__half2 v) { return __low2half2(v); }
__device__ __forceinline__ __half2 hi2(__half2 v) { return __high2half2(v); }

__global__ void __launch_bounds__(128, 12) sim_kernel(
    const float* __restrict__ omega,
    const float* __restrict__ Wh1, const float* __restrict__ bh1,
    const float* __restrict__ Wh2, const float* __restrict__ bh2,
    const float* __restrict__ Wr1, const float* __restrict__ br1,
    const float* __restrict__ Wr2, const float* __restrict__ br2,
    const float* __restrict__ alpha,
    float* __restrict__ out,
    int n)
{
    const int half = n >> 1;           // n is even (1048576)
    const int i = blockIdx.x * blockDim.x + threadIdx.x;

    float v1 = 0.0f, v2 = 0.0f;

    if (i < half) {
        // Two tasks per thread: lane-lo = task i, lane-hi = task i+half.
        const float st0_lo = omega[i],     st0_hi = omega[i + half];
        const float st1_lo = omega[n + i], st1_hi = omega[n + i + half];
        const u64 star0 = pack2(st0_lo, st0_hi);
        const u64 star1 = pack2(st1_lo, st1_hi);

        // ---- lane-packed half2 weights (two distinct weights per register) ----
        // Human layer1: star part folded into per-task bias c_h; loop keeps
        // only W[j,2]*s0 + W[j,3]*s1. whAB[j] = (W[j,2], W[j,3]).
        __half2 whAB[4], c_h[4];
#pragma unroll
        for (int j = 0; j < 4; j++) {
            float w0 = __ldg(Wh1 + 4*j + 0), w1 = __ldg(Wh1 + 4*j + 1);
            float w2 = __ldg(Wh1 + 4*j + 2), w3 = __ldg(Wh1 + 4*j + 3);
            float b  = __ldg(bh1 + j);
            float clo = fmaf(w0, st0_lo, fmaf(w1, st1_lo, b));
            float chi = fmaf(w0, st0_hi, fmaf(w1, st1_hi, b));
            c_h[j] = __floats2half2_rn(clo, chi);
            whAB[j] = __floats2half2_rn(w2, w3);
        }
        // Human layer2: wh2_01=(w0,w1), wh2_2b3=(w2,w3), bias packed with threshold.
        const __half2 wh2_01 = __floats2half2_rn(__ldg(Wh2 + 0), __ldg(Wh2 + 1));
        const __half2 wh2_23 = __floats2half2_rn(__ldg(Wh2 + 2), __ldg(Wh2 + 3));
        const __half2 bh2_thr = __floats2half2_rn(__ldg(bh2), 0.01f);  // (bias, eff-threshold)

        // Robot layer1: wrS[j]=(W[j,0],W[j,1]), wrZB[j]=(W[j,2], b[j]).
        __half2 wrS[3], wrZB[3];
#pragma unroll
        for (int j = 0; j < 3; j++) {
            wrS[j]  = __floats2half2_rn(__ldg(Wr1 + 3*j + 0), __ldg(Wr1 + 3*j + 1));
            wrZB[j] = __floats2half2_rn(__ldg(Wr1 + 3*j + 2), __ldg(br1 + j));
        }
        // Robot layer2: wr2_01=(w0,w1), wr2_2b=(w2, b).
        const __half2 wr2_01 = __floats2half2_rn(__ldg(Wr2 + 0), __ldg(Wr2 + 1));
        const __half2 wr2_2b = __floats2half2_rn(__ldg(Wr2 + 2), __ldg(br2));

        const u64 neg1 = pack2(-1.0f, -1.0f);
        const u64 c01  = pack2(0.1f, 0.1f);
        const u64 dt2  = pack2(DT, DT);

        u64 s0 = 0ull, s1 = 0ull;           // packed (0.0f, 0.0f)
        u64 err0 = 0ull, err1 = 0ull;       // Sum e0^2, Sum e1^2 (x10 applied at end)
        u64 nor = 0ull;
        __half2 eff = __float2half2_rn(0.0f);  // integer counts <= 40, exact in f16

#pragma unroll 1
        for (int t = 0; t < N_STEPS - 1; t++) {
            // f32x2 outer dynamics
            u64 e0 = fma2(neg1, s0, star0);
            u64 e1 = fma2(neg1, s1, star1);
            err0 = fma2(e0, e0, err0);
            err1 = fma2(e1, e1, err1);
            u64 zt = fma2(c01, e1, e0);

            // state -> half2
            float s0lo, s0hi, s1lo, s1hi;
            unpack2(s0, s0lo, s0hi);
            unpack2(s1, s1lo, s1hi);
            __half2 s0h = __floats2half2_rn(s0lo, s0hi);
            __half2 s1h = __floats2half2_rn(s1lo, s1hi);

            // human MLP (star part folded into c_h), lane-select weights
            __half2 h0 = tanh_h2(__hfma2(hi2(whAB[0]), s1h, __hfma2(lo2(whAB[0]), s0h, c_h[0])));
            __half2 h1 = tanh_h2(__hfma2(hi2(whAB[1]), s1h, __hfma2(lo2(whAB[1]), s0h, c_h[1])));
            __half2 h2 = tanh_h2(__hfma2(hi2(whAB[2]), s1h, __hfma2(lo2(whAB[2]), s0h, c_h[2])));
            __half2 h3 = tanh_h2(__hfma2(hi2(whAB[3]), s1h, __hfma2(lo2(whAB[3]), s0h, c_h[3])));
            __half2 z  = tanh_h2(__hfma2(hi2(wh2_23), h3, __hfma2(lo2(wh2_23), h2,
                                 __hfma2(hi2(wh2_01), h1, __hfma2(lo2(wh2_01), h0, lo2(bh2_thr))))));

            // robot MLP
            __half2 r0 = tanh_h2(__hfma2(lo2(wrZB[0]), z, __hfma2(hi2(wrS[0]), s1h,
                                 __hfma2(lo2(wrS[0]), s0h, hi2(wrZB[0])))));
            __half2 r1 = tanh_h2(__hfma2(lo2(wrZB[1]), z, __hfma2(hi2(wrS[1]), s1h,
                                 __hfma2(lo2(wrS[1]), s0h, hi2(wrZB[1])))));
            __half2 r2 = tanh_h2(__hfma2(lo2(wrZB[2]), z, __hfma2(hi2(wrS[2]), s1h,
                                 __hfma2(lo2(wrS[2]), s0h, hi2(wrZB[2])))));
            __half2 ah = __hfma2(lo2(wr2_2b), r2, __hfma2(hi2(wr2_01), r1,
                                 __hfma2(lo2(wr2_01), r0, hi2(wr2_2b))));

            // state update in f32x2
            float2 af = __half22float2(ah);
            s0 = fma2(dt2, s1, s0);
            s1 = fma2(dt2, pack2(af.x, af.y), s1);

            // eff: half2 compare gives 1.0/0.0 per lane
            eff = __hadd2(eff, __hgt2(__habs2(z), hi2(bh2_thr)));

            // nor in f32x2
            float2 zf = __half22float2(z);
            u64 d = fma2(neg1, pack2(zf.x, zf.y), zt);
            nor = fma2(d, d, nor);
        }

        // final error term
        u64 e0 = fma2(neg1, s0, star0);
        u64 e1 = fma2(neg1, s1, star1);
        err0 = fma2(e0, e0, err0);
        err1 = fma2(e1, e1, err1);

        float e0lo, e0hi, e1lo, e1hi, nor_lo, nor_hi;
        unpack2(err0, e0lo, e0hi);
        unpack2(err1, e1lo, e1hi);
        unpack2(nor, nor_lo, nor_hi);
        float2 efff = __half22float2(eff);
        v1 = (fmaf(10.0f, e0lo, e1lo) + efff.x) + (fmaf(10.0f, e0hi, e1hi) + efff.y);
        v2 = nor_lo + nor_hi;
    }

    // warp reduce
#pragma unroll
    for (int off = 16; off > 0; off >>= 1) {
        v1 += __shfl_down_sync(0xFFFFFFFFu, v1, off);
        v2 += __shfl_down_sync(0xFFFFFFFFu, v2, off);
    }

    __shared__ float s1buf[4];
    __shared__ float s2buf[4];
    int lane = threadIdx.x & 31;
    int wid  = threadIdx.x >> 5;
    if (lane == 0) { s1buf[wid] = v1; s2buf[wid] = v2; }
    __syncthreads();

    __shared__ bool is_last;
    if (threadIdx.x == 0) {
        float a1 = s1buf[0] + s1buf[1] + s1buf[2] + s1buf[3];
        float a2 = s2buf[0] + s2buf[1] + s2buf[2] + s2buf[3];
        atomicAdd(&g_acc[0], (double)a1);
        atomicAdd(&g_acc[1], (double)a2);
        __threadfence();
        unsigned int ticket = atomicAdd(&g_count, 1u);
        is_last = (ticket == gridDim.x - 1);
    }
    __syncthreads();

    // Tail block: finalize and reset accumulators for the next graph replay.
    if (is_last && threadIdx.x == 0) {
        double tot = (g_acc[0] + (double)alpha[0] * g_acc[1]) / (double)n;
        out[0] = (float)tot;
        g_acc[0] = 0.0;
        g_acc[1] = 0.0;
        g_count  = 0u;
        __threadfence();
    }
}

extern "C" void kernel_launch(void* const* d_in, const int* in_sizes, int n_in,
                              void* d_out, int out_size) {
    const float* omega = (const float*)d_in[0];
    const float* Wh1   = (const float*)d_in[1];
    const float* bh1   = (const float*)d_in[2];
    const float* Wh2   = (const float*)d_in[3];
    const float* bh2   = (const float*)d_in[4];
    const float* Wr1   = (const float*)d_in[5];
    const float* br1   = (const float*)d_in[6];
    const float* Wr2   = (const float*)d_in[7];
    const float* br2   = (const float*)d_in[8];
    const float* alpha = (const float*)d_in[9];
    float* out = (float*)d_out;

    int n = in_sizes[0] / 2;  // omega is [2, N]
    int half = n >> 1;

    int threads = 128;
    int blocks = (half + threads - 1) / threads;
    sim_kernel<<<blocks, threads>>>(omega, Wh1, bh1, Wh2, bh2, Wr1, br1, Wr2, br2,
                                    alpha, out, n);
}

// round 6
// speedup vs baseline: 1.0739x; 1.0523x over previous
#include <cuda_runtime.h>
#include <cuda_fp16.h>

#define DT 0.05f
#define N_STEPS 41

typedef unsigned long long u64;

// Global accumulators: [0] = sum(err+eff), [1] = sum(nor). Zero-initialized at
// module load; the LAST block of each launch resets them after reading, so the
// kernel is replay-deterministic under graph capture.
__device__ double g_acc[2] = {0.0, 0.0};
__device__ unsigned int g_count = 0;

// ---- f32x2 packed helpers (SASS FFMA2 — only reachable via PTX) ----
__device__ __forceinline__ u64 pack2(float lo, float hi) {
    u64 r; asm("mov.b64 %0, {%1, %2};" : "=l"(r) : "f"(lo), "f"(hi)); return r;
}
__device__ __forceinline__ void unpack2(u64 v, float& lo, float& hi) {
    asm("mov.b64 {%0, %1}, %2;" : "=f"(lo), "=f"(hi) : "l"(v));
}
__device__ __forceinline__ u64 fma2(u64 a, u64 b, u64 c) {
    u64 d; asm("fma.rn.f32x2 %0, %1, %2, %3;" : "=l"(d) : "l"(a), "l"(b), "l"(c)); return d;
}

// tanh on a half2 (both lanes), one MUFU op, no conversions.
__device__ __forceinline__ __half2 tanh_h2(__half2 x) {
    unsigned int b = *reinterpret_cast<unsigned int*>(&x);
    asm("tanh.approx.f16x2 %0, %0;" : "+r"(b));
    return *reinterpret_cast<__half2*>(&b);
}

// Broadcast one lane of a packed half2 — folds into HFMA2 half-lane-select
// source modifiers (.H0_H0 / .H1_H1).
__device__ __forceinline__ __half2 lo2(__half2 v) { return __low2half2(v); }
__device__ __forceinline__ __half2 hi2(__half2 v) { return __high2half2(v); }

__global__ void __launch_bounds__(128) sim_kernel(
    const float* __restrict__ omega,
    const float* __restrict__ Wh1, const float* __restrict__ bh1,
    const float* __restrict__ Wh2, const float* __restrict__ bh2,
    const float* __restrict__ Wr1, const float* __restrict__ br1,
    const float* __restrict__ Wr2, const float* __restrict__ br2,
    const float* __restrict__ alpha,
    float* __restrict__ out,
    int n)
{
    const int half = n >> 1;           // n is even (1048576)
    const int i = blockIdx.x * blockDim.x + threadIdx.x;

    float v1 = 0.0f, v2 = 0.0f;

    if (i < half) {
        // Two tasks per thread: lane-lo = task i, lane-hi = task i+half.
        const float st0_lo = omega[i],     st0_hi = omega[i + half];
        const float st1_lo = omega[n + i], st1_hi = omega[n + i + half];
        const u64 star0 = pack2(st0_lo, st0_hi);
        const u64 star1 = pack2(st1_lo, st1_hi);
        const __half2 star0h = __floats2half2_rn(st0_lo, st0_hi);
        const __half2 star1h = __floats2half2_rn(st1_lo, st1_hi);

        // ---- lane-packed half2 weights ----
        // Human layer1: star part folded into per-task bias c_h; loop keeps
        // only W[j,2]*s0 + W[j,3]*s1. whAB[j] = (W[j,2], W[j,3]).
        __half2 whAB[4], c_h[4];
#pragma unroll
        for (int j = 0; j < 4; j++) {
            float w0 = __ldg(Wh1 + 4*j + 0), w1 = __ldg(Wh1 + 4*j + 1);
            float w2 = __ldg(Wh1 + 4*j + 2), w3 = __ldg(Wh1 + 4*j + 3);
            float b  = __ldg(bh1 + j);
            float clo = fmaf(w0, st0_lo, fmaf(w1, st1_lo, b));
            float chi = fmaf(w0, st0_hi, fmaf(w1, st1_hi, b));
            c_h[j] = __floats2half2_rn(clo, chi);
            whAB[j] = __floats2half2_rn(w2, w3);
        }
        const __half2 wh2_01 = __floats2half2_rn(__ldg(Wh2 + 0), __ldg(Wh2 + 1));
        const __half2 wh2_23 = __floats2half2_rn(__ldg(Wh2 + 2), __ldg(Wh2 + 3));
        const __half2 bh2_thr = __floats2half2_rn(__ldg(bh2), 0.01f);  // (bias, eff-threshold)

        __half2 wrS[3], wrZB[3];
#pragma unroll
        for (int j = 0; j < 3; j++) {
            wrS[j]  = __floats2half2_rn(__ldg(Wr1 + 3*j + 0), __ldg(Wr1 + 3*j + 1));
            wrZB[j] = __floats2half2_rn(__ldg(Wr1 + 3*j + 2), __ldg(br1 + j));
        }
        const __half2 wr2_01 = __floats2half2_rn(__ldg(Wr2 + 0), __ldg(Wr2 + 1));
        const __half2 wr2_2b = __floats2half2_rn(__ldg(Wr2 + 2), __ldg(br2));

        // c01_dt packs (0.1 for zt, unused) — keep 0.1 broadcastable.
        const __half2 c01h = __float2half2_rn(0.1f);

        const u64 neg1 = pack2(-1.0f, -1.0f);
        const u64 dt2  = pack2(DT, DT);

        u64 s0 = 0ull, s1 = 0ull;           // packed f32x2 state (precision-critical)
        u64 err0 = 0ull, err1 = 0ull;       // Sum e0^2, Sum e1^2 (x10 applied at end)
        __half2 norh = __float2half2_rn(0.0f);
        __half2 eff  = __float2half2_rn(0.0f);

#pragma unroll 4
        for (int t = 0; t < N_STEPS - 1; t++) {
            // f32x2: error + err accumulation (precision-critical path)
            u64 e0 = fma2(neg1, s0, star0);
            u64 e1 = fma2(neg1, s1, star1);
            err0 = fma2(e0, e0, err0);
            err1 = fma2(e1, e1, err1);

            // single crossing: state -> half2 (also used for zt path)
            float s0lo, s0hi, s1lo, s1hi;
            unpack2(s0, s0lo, s0hi);
            unpack2(s1, s1lo, s1hi);
            __half2 s0h = __floats2half2_rn(s0lo, s0hi);
            __half2 s1h = __floats2half2_rn(s1lo, s1hi);

            // zt in half2: e0h + 0.1*e1h
            __half2 e0h = __hsub2(star0h, s0h);
            __half2 e1h = __hsub2(star1h, s1h);
            __half2 zth = __hfma2(c01h, e1h, e0h);

            // human MLP (star part folded into c_h), lane-select weights
            __half2 h0 = tanh_h2(__hfma2(hi2(whAB[0]), s1h, __hfma2(lo2(whAB[0]), s0h, c_h[0])));
            __half2 h1 = tanh_h2(__hfma2(hi2(whAB[1]), s1h, __hfma2(lo2(whAB[1]), s0h, c_h[1])));
            __half2 h2 = tanh_h2(__hfma2(hi2(whAB[2]), s1h, __hfma2(lo2(whAB[2]), s0h, c_h[2])));
            __half2 h3 = tanh_h2(__hfma2(hi2(whAB[3]), s1h, __hfma2(lo2(whAB[3]), s0h, c_h[3])));
            __half2 z  = tanh_h2(__hfma2(hi2(wh2_23), h3, __hfma2(lo2(wh2_23), h2,
                                 __hfma2(hi2(wh2_01), h1, __hfma2(lo2(wh2_01), h0, lo2(bh2_thr))))));

            // robot MLP
            __half2 r0 = tanh_h2(__hfma2(lo2(wrZB[0]), z, __hfma2(hi2(wrS[0]), s1h,
                                 __hfma2(lo2(wrS[0]), s0h, hi2(wrZB[0])))));
            __half2 r1 = tanh_h2(__hfma2(lo2(wrZB[1]), z, __hfma2(hi2(wrS[1]), s1h,
                                 __hfma2(lo2(wrS[1]), s0h, hi2(wrZB[1])))));
            __half2 r2 = tanh_h2(__hfma2(lo2(wrZB[2]), z, __hfma2(hi2(wrS[2]), s1h,
                                 __hfma2(lo2(wrS[2]), s0h, hi2(wrZB[2])))));
            __half2 ah = __hfma2(lo2(wr2_2b), r2, __hfma2(hi2(wr2_01), r1,
                                 __hfma2(lo2(wr2_01), r0, hi2(wr2_2b))));

            // crossing: a -> f32x2 for the precision-critical state update
            float2 af = __half22float2(ah);
            s0 = fma2(dt2, s1, s0);
            s1 = fma2(dt2, pack2(af.x, af.y), s1);

            // eff + nor fully in half2
            eff = __hadd2(eff, __hgt2(__habs2(z), hi2(bh2_thr)));
            __half2 d = __hsub2(zth, z);
            norh = __hfma2(d, d, norh);
        }

        // final error term
        u64 e0 = fma2(neg1, s0, star0);
        u64 e1 = fma2(neg1, s1, star1);
        err0 = fma2(e0, e0, err0);
        err1 = fma2(e1, e1, err1);

        float e0lo, e0hi, e1lo, e1hi;
        unpack2(err0, e0lo, e0hi);
        unpack2(err1, e1lo, e1hi);
        float2 efff = __half22float2(eff);
        float2 norf = __half22float2(norh);
        v1 = (fmaf(10.0f, e0lo, e1lo) + efff.x) + (fmaf(10.0f, e0hi, e1hi) + efff.y);
        v2 = norf.x + norf.y;
    }

    // warp reduce
#pragma unroll
    for (int off = 16; off > 0; off >>= 1) {
        v1 += __shfl_down_sync(0xFFFFFFFFu, v1, off);
        v2 += __shfl_down_sync(0xFFFFFFFFu, v2, off);
    }

    __shared__ float s1buf[4];
    __shared__ float s2buf[4];
    int lane = threadIdx.x & 31;
    int wid  = threadIdx.x >> 5;
    if (lane == 0) { s1buf[wid] = v1; s2buf[wid] = v2; }
    __syncthreads();

    __shared__ bool is_last;
    if (threadIdx.x == 0) {
        float a1 = s1buf[0] + s1buf[1] + s1buf[2] + s1buf[3];
        float a2 = s2buf[0] + s2buf[1] + s2buf[2] + s2buf[3];
        atomicAdd(&g_acc[0], (double)a1);
        atomicAdd(&g_acc[1], (double)a2);
        __threadfence();
        unsigned int ticket = atomicAdd(&g_count, 1u);
        is_last = (ticket == gridDim.x - 1);
    }
    __syncthreads();

    // Tail block: finalize and reset accumulators for the next graph replay.
    if (is_last && threadIdx.x == 0) {
        double tot = (g_acc[0] + (double)alpha[0] * g_acc[1]) / (double)n;
        out[0] = (float)tot;
        g_acc[0] = 0.0;
        g_acc[1] = 0.0;
        g_count  = 0u;
        __threadfence();
    }
}

extern "C" void kernel_launch(void* const* d_in, const int* in_sizes, int n_in,
                              void* d_out, int out_size) {
    const float* omega = (const float*)d_in[0];
    const float* Wh1   = (const float*)d_in[1];
    const float* bh1   = (const float*)d_in[2];
    const float* Wh2   = (const float*)d_in[3];
    const float* bh2   = (const float*)d_in[4];
    const float* Wr1   = (const float*)d_in[5];
    const float* br1   = (const float*)d_in[6];
    const float* Wr2   = (const float*)d_in[7];
    const float* br2   = (const float*)d_in[8];
    const float* alpha = (const float*)d_in[9];
    float* out = (float*)d_out;

    int n = in_sizes[0] / 2;  // omega is [2, N]
    int half = n >> 1;

    int threads = 128;
    int blocks = (half + threads - 1) / threads;
    sim_kernel<<<blocks, threads>>>(omega, Wh1, bh1, Wh2, bh2, Wr1, br1, Wr2, br2,
                                    alpha, out, n);
}